// round 7
// baseline (speedup 1.0000x reference)
#include <cuda_runtime.h>
#include <cstdint>

#define NMAX   100000
#define EMAX   500000
#define DIM    128
#define NHEAD  4
#define HD     32
#define NBLK   391          // ceil(NMAX/256)

// ---------------- scratch ----------------
__device__ float g_h32[NMAX * HD];
__device__ float g_eas[NMAX * NHEAD];   // exp(alpha_src)
__device__ float g_ead[NMAX * NHEAD];   // exp(alpha_dst)
__device__ float g_sums[NHEAD];
__device__ float g_WT[DIM * DIM];       // [k][o]
__device__ int   g_is64;
__device__ int   g_cnt[NMAX];
__device__ int   g_intra[NMAX];         // global exclusive offsets (after scan)
__device__ int2  g_sd[EMAX];            // (src, dst)
__device__ int   g_rk[EMAX];
__device__ int   g_esrc[EMAX];
// lookback scan state
__device__ int   g_flag[NBLK];
__device__ int   g_agg[NBLK];
__device__ int   g_incv[NBLK];

// ---------------- K0: prep ----------------
__global__ void prep_kernel(const float* __restrict__ Wlin,
                            const unsigned int* __restrict__ ei_raw) {
    int tid = blockIdx.x * blockDim.x + threadIdx.x;
    int total = gridDim.x * blockDim.x;
    for (int i = tid; i < NMAX; i += total) g_cnt[i] = 0;
    for (int i = tid; i < NBLK; i += total) g_flag[i] = 0;
    for (int i = tid; i < DIM * DIM; i += total) {
        int o = i >> 7, k = i & 127;
        g_WT[k * DIM + o] = Wlin[i];
    }
    if (blockIdx.x == 0) {
        if (threadIdx.x < NHEAD) g_sums[threadIdx.x] = 0.0f;
        if (threadIdx.x == 0) {
            int all0 = 1;
            for (int i = 0; i < 64; i++)
                if (ei_raw[2 * i + 1] != 0u) { all0 = 0; break; }
            g_is64 = all0;
        }
    }
}

// ---------------- K1: FFMA2 GEMM + alpha/exp epilogue (R2-proven) ----------------
#define XCH_STRIDE 132
#define GEMM_SMEM  (16384 * 4 + 2 * 32 * XCH_STRIDE * 4)

__global__ __launch_bounds__(256, 2)
void gemm_kernel(const float* __restrict__ X,
                 const float* __restrict__ blin,
                 const float* __restrict__ Watt,
                 float* __restrict__ out, int N) {
    extern __shared__ float sm[];
    unsigned long long* Wp = (unsigned long long*)sm;   // [k][pos] pos(q)=(q&3)*16+(q>>2)
    float* Xs = sm + 16384;                             // [buf][k][m], stride 132
    __shared__ float sWa[NHEAD * 2 * DIM];
    __shared__ float sb[DIM];

    int tid = threadIdx.x;
    for (int i = tid; i < NHEAD * 2 * DIM; i += 256) sWa[i] = Watt[i];
    if (tid < DIM) sb[tid] = blin[tid];

    // W: g_WT [k][o] -> pair-swizzled u64 layout (conflict-free b reads)
    for (int i = tid; i < DIM * 32; i += 256) {
        int k = i >> 5, cq = i & 31;
        float4 w4 = ((const float4*)g_WT)[i];
        int q0 = 2 * cq, q1 = 2 * cq + 1;
        int pos0 = (q0 & 3) * 16 + (q0 >> 2);
        int pos1 = (q1 & 3) * 16 + (q1 >> 2);
        unsigned long long lo, hi;
        asm("mov.b64 %0, {%1, %2};" : "=l"(lo) : "r"(__float_as_uint(w4.x)), "r"(__float_as_uint(w4.y)));
        asm("mov.b64 %0, {%1, %2};" : "=l"(hi) : "r"(__float_as_uint(w4.z)), "r"(__float_as_uint(w4.w)));
        Wp[k * 64 + pos0] = lo;
        Wp[k * 64 + pos1] = hi;
    }

    int row0 = blockIdx.x * 128;
    float4 xreg[4];

    auto loadX = [&](int ch) {
        #pragma unroll
        for (int t = 0; t < 4; t++) {
            int idx = tid + t * 256;
            int m = idx >> 3, kq = idx & 7;
            xreg[t] = make_float4(0.f, 0.f, 0.f, 0.f);
            if (row0 + m < N)
                xreg[t] = ((const float4*)X)[(size_t)(row0 + m) * 32 + ch * 8 + kq];
        }
    };
    auto storeX = [&](int buf) {
        float* base = &Xs[buf * 32 * XCH_STRIDE];
        #pragma unroll
        for (int t = 0; t < 4; t++) {
            int idx = tid + t * 256;
            int m = idx >> 3, kq = idx & 7;
            base[(kq * 4 + 0) * XCH_STRIDE + m] = xreg[t].x;
            base[(kq * 4 + 1) * XCH_STRIDE + m] = xreg[t].y;
            base[(kq * 4 + 2) * XCH_STRIDE + m] = xreg[t].z;
            base[(kq * 4 + 3) * XCH_STRIDE + m] = xreg[t].w;
        }
    };

    loadX(0); storeX(0);
    __syncthreads();

    int tx = tid & 15, ty = tid >> 4;
    int c = tx * 8;

    unsigned long long acc[8][4];
    #pragma unroll
    for (int r = 0; r < 8; r++)
        #pragma unroll
        for (int p = 0; p < 4; p++) acc[r][p] = 0ull;

    for (int ch = 0; ch < 4; ch++) {
        if (ch < 3) loadX(ch + 1);
        int buf = ch & 1;
        const float* xb = &Xs[buf * 32 * XCH_STRIDE];
        #pragma unroll 8
        for (int k = 0; k < 32; k++) {
            float4 a0 = *(const float4*)&xb[k * XCH_STRIDE + ty * 8];
            float4 a1 = *(const float4*)&xb[k * XCH_STRIDE + ty * 8 + 4];
            unsigned long long arep[8];
            const float* av = &a0.x;
            #pragma unroll
            for (int r = 0; r < 4; r++)
                asm("mov.b64 %0, {%1, %1};" : "=l"(arep[r]) : "r"(__float_as_uint(av[r])));
            const float* av1 = &a1.x;
            #pragma unroll
            for (int r = 0; r < 4; r++)
                asm("mov.b64 %0, {%1, %1};" : "=l"(arep[4 + r]) : "r"(__float_as_uint(av1[r])));
            const unsigned long long* wrow = &Wp[(ch * 32 + k) * 64];
            #pragma unroll
            for (int p = 0; p < 4; p++) {
                unsigned long long b = wrow[p * 16 + tx];
                #pragma unroll
                for (int r = 0; r < 8; r++)
                    asm("fma.rn.f32x2 %0, %1, %2, %0;" : "+l"(acc[r][p]) : "l"(arep[r]), "l"(b));
            }
        }
        if (ch < 3) {
            __syncthreads();
            storeX(buf ^ 1);
            __syncthreads();
        }
    }

    // epilogue
    float hv[8][8];
    #pragma unroll
    for (int r = 0; r < 8; r++)
        #pragma unroll
        for (int p = 0; p < 4; p++) {
            float lo = __uint_as_float((unsigned)(acc[r][p] & 0xffffffffull));
            float hi = __uint_as_float((unsigned)(acc[r][p] >> 32));
            hv[r][2 * p]     = lo + sb[c + 2 * p];
            hv[r][2 * p + 1] = hi + sb[c + 2 * p + 1];
        }

    #pragma unroll
    for (int r = 0; r < 8; r++) {
        int row = row0 + ty * 8 + r;
        if (row < N) {
            float4 v0 = make_float4(hv[r][0], hv[r][1], hv[r][2], hv[r][3]);
            float4 v1 = make_float4(hv[r][4], hv[r][5], hv[r][6], hv[r][7]);
            ((float4*)out)[(size_t)row * 32 + tx * 2]     = v0;
            ((float4*)out)[(size_t)row * 32 + tx * 2 + 1] = v1;
            if (tx < 4) {
                ((float4*)g_h32)[row * 8 + tx * 2]     = v0;
                ((float4*)g_h32)[row * 8 + tx * 2 + 1] = v1;
            }
        }
    }

    #pragma unroll
    for (int r = 0; r < 8; r++) {
        int row = row0 + ty * 8 + r;
        float ps[NHEAD], pd[NHEAD];
        #pragma unroll
        for (int hh = 0; hh < NHEAD; hh++) {
            float s1 = 0.f, s2 = 0.f;
            #pragma unroll
            for (int j = 0; j < 8; j++) {
                s1 += hv[r][j] * sWa[hh * 2 * DIM + c + j];
                s2 += hv[r][j] * sWa[hh * 2 * DIM + DIM + c + j];
            }
            #pragma unroll
            for (int off = 8; off; off >>= 1) {
                s1 += __shfl_down_sync(0xffffffffu, s1, off, 16);
                s2 += __shfl_down_sync(0xffffffffu, s2, off, 16);
            }
            ps[hh] = s1; pd[hh] = s2;
        }
        if (tx == 0 && row < N) {
            ((float4*)g_eas)[row] = make_float4(__expf(ps[0]), __expf(ps[1]), __expf(ps[2]), __expf(ps[3]));
            ((float4*)g_ead)[row] = make_float4(__expf(pd[0]), __expf(pd[1]), __expf(pd[2]), __expf(pd[3]));
        }
    }
}

// ---------------- K2: edge pass (decode + hist/rank + softmax sums) ----------------
__global__ __launch_bounds__(256)
void edge_kernel(const void* __restrict__ ei, int E) {
    int e = blockIdx.x * 256 + threadIdx.x;
    float v0 = 0.f, v1 = 0.f, v2 = 0.f, v3 = 0.f;
    if (e < E) {
        int s, d;
        if (g_is64) {
            const long long* p = (const long long*)ei;
            s = (int)p[e]; d = (int)p[E + e];
        } else {
            const int* p = (const int*)ei;
            s = p[e]; d = p[E + e];
        }
        g_sd[e] = make_int2(s, d);
        g_rk[e] = atomicAdd(&g_cnt[d], 1);
        float4 as = ((const float4*)g_eas)[s];
        float4 ad = ((const float4*)g_ead)[d];
        v0 = as.x * ad.x; v1 = as.y * ad.y; v2 = as.z * ad.z; v3 = as.w * ad.w;
    }
    #pragma unroll
    for (int off = 16; off; off >>= 1) {
        v0 += __shfl_xor_sync(0xffffffffu, v0, off);
        v1 += __shfl_xor_sync(0xffffffffu, v1, off);
        v2 += __shfl_xor_sync(0xffffffffu, v2, off);
        v3 += __shfl_xor_sync(0xffffffffu, v3, off);
    }
    __shared__ float ss[NHEAD];
    if (threadIdx.x < NHEAD) ss[threadIdx.x] = 0.f;
    __syncthreads();
    if ((threadIdx.x & 31) == 0) {
        atomicAdd(&ss[0], v0); atomicAdd(&ss[1], v1);
        atomicAdd(&ss[2], v2); atomicAdd(&ss[3], v3);
    }
    __syncthreads();
    if (threadIdx.x < NHEAD) atomicAdd(&g_sums[threadIdx.x], ss[threadIdx.x]);
}

// ---------------- K3: single-kernel decoupled-lookback scan ----------------
// writes GLOBAL exclusive offsets into g_intra
__global__ __launch_bounds__(256)
void scan_kernel() {
    int t = threadIdx.x;
    int bid = blockIdx.x;
    int i = bid * 256 + t;
    int v = (i < NMAX) ? g_cnt[i] : 0;
    int x = v;
    #pragma unroll
    for (int off = 1; off < 32; off <<= 1) {
        int y = __shfl_up_sync(0xffffffffu, x, off);
        if ((t & 31) >= off) x += y;
    }
    __shared__ int wsum[8];
    if ((t & 31) == 31) wsum[t >> 5] = x;
    __syncthreads();
    if (t < 8) {
        int y = wsum[t], z = y;
        #pragma unroll
        for (int off = 1; off < 8; off <<= 1) {
            int q = __shfl_up_sync(0xffu, z, off);
            if (t >= off) z += q;
        }
        wsum[t] = z - y;
    }
    __syncthreads();
    int excl = x - v + wsum[t >> 5];           // exclusive within block

    __shared__ int s_prev;
    if (t == 255) {
        int agg = excl + v;
        g_agg[bid] = agg;
        __threadfence();
        atomicExch(&g_flag[bid], 1);
        int run = 0;
        for (int p = bid - 1; p >= 0; p--) {
            int f;
            do { f = atomicAdd(&g_flag[p], 0); } while (f == 0);
            if (f == 2) { run += atomicAdd(&g_incv[p], 0); break; }
            run += atomicAdd(&g_agg[p], 0);
        }
        g_incv[bid] = run + agg;
        __threadfence();
        atomicExch(&g_flag[bid], 2);
        s_prev = run;
    }
    __syncthreads();
    if (i < NMAX) g_intra[i] = s_prev + excl;
}

// ---------------- K4: CSR fill (atomic-free) ----------------
__global__ __launch_bounds__(256)
void fill_kernel(int E) {
    int e = blockIdx.x * 256 + threadIdx.x;
    if (e >= E) return;
    int2 sd = g_sd[e];
    g_esrc[g_intra[sd.y] + g_rk[e]] = sd.x;
}

// ---------------- K5: gather ----------------
__global__ __launch_bounds__(256)
void gather_kernel(float* __restrict__ out, int N) {
    int d = (blockIdx.x * 256 + threadIdx.x) >> 5;
    int lane = threadIdx.x & 31;
    if (d >= N) return;
    int n = g_cnt[d];
    if (n == 0) return;                 // out already holds h
    int base = g_intra[d];
    float4 fe = ((const float4*)g_ead)[d];
    float4 sm4 = *(const float4*)g_sums;
    float w0 = __fdividef(fe.x, sm4.x);
    float w1 = __fdividef(fe.y, sm4.y);
    float w2 = __fdividef(fe.z, sm4.z);
    float w3 = __fdividef(fe.w, sm4.w);
    float a0 = 0.f, a1 = 0.f, a2 = 0.f, a3 = 0.f;
    for (int i = 0; i < n; i++) {
        int s = g_esrc[base + i];
        float v = g_h32[s * HD + lane];
        float4 ea = ((const float4*)g_eas)[s];
        a0 += v * ea.x; a1 += v * ea.y; a2 += v * ea.z; a3 += v * ea.w;
    }
    float* o = out + (size_t)d * DIM + lane;
    o[0]  += a0 * w0;
    o[32] += a1 * w1;
    o[64] += a2 * w2;
    o[96] += a3 * w3;
}

// ---------------- launch ----------------
extern "C" void kernel_launch(void* const* d_in, const int* in_sizes, int n_in,
                              void* d_out, int out_size) {
    const float* X    = (const float*)d_in[0];
    const void*  ei   = d_in[1];
    const float* Wlin = (const float*)d_in[2];
    const float* blin = (const float*)d_in[3];
    const float* Watt = (const float*)d_in[4];
    float* out = (float*)d_out;

    int N = in_sizes[0] / DIM;
    int E = in_sizes[1] / 2;

    cudaFuncSetAttribute(gemm_kernel,
                         cudaFuncAttributeMaxDynamicSharedMemorySize, GEMM_SMEM);

    prep_kernel<<<200, 512>>>(Wlin, (const unsigned int*)ei);
    gemm_kernel<<<(N + 127) / 128, 256, GEMM_SMEM>>>(X, blin, Watt, out, N);
    edge_kernel<<<(E + 255) / 256, 256>>>(ei, E);
    scan_kernel<<<NBLK, 256>>>();
    fill_kernel<<<(E + 255) / 256, 256>>>(E);
    gather_kernel<<<(N * 32 + 255) / 256, 256>>>(out, N);
}

// round 8
// speedup vs baseline: 1.1915x; 1.1915x over previous
#include <cuda_runtime.h>
#include <cstdint>

#define NMAX   100000
#define EMAX   500000
#define DIM    128
#define NHEAD  4
#define HD     32
#define NBLK   391          // ceil(NMAX/256)

// ---------------- scratch ----------------
__device__ float g_h32[NMAX * HD];
__device__ float g_eas[NMAX * NHEAD];   // exp(alpha_src)
__device__ float g_ead[NMAX * NHEAD];   // exp(alpha_dst)
__device__ float g_sums[NHEAD];
__device__ float g_WT[DIM * DIM];       // [k][o]
__device__ int   g_is64;
__device__ int   g_cnt[NMAX];
__device__ int   g_intra[NMAX];         // intra-block exclusive offsets
__device__ int   g_bsum[512];
__device__ int   g_boff[512];
__device__ int2  g_sd[EMAX];            // (src, dst)
__device__ int   g_rk[EMAX];
__device__ int   g_esrc[EMAX];

// ---------------- K0: prep ----------------
__global__ void prep_kernel(const float* __restrict__ Wlin,
                            const unsigned int* __restrict__ ei_raw) {
    int tid = blockIdx.x * blockDim.x + threadIdx.x;
    int total = gridDim.x * blockDim.x;
    for (int i = tid; i < NMAX; i += total) g_cnt[i] = 0;
    for (int i = tid; i < DIM * DIM; i += total) {
        int o = i >> 7, k = i & 127;
        g_WT[k * DIM + o] = Wlin[i];
    }
    if (blockIdx.x == 0) {
        if (threadIdx.x < NHEAD) g_sums[threadIdx.x] = 0.0f;
        if (threadIdx.x == 0) {
            int all0 = 1;
            for (int i = 0; i < 64; i++)
                if (ei_raw[2 * i + 1] != 0u) { all0 = 0; break; }
            g_is64 = all0;
        }
    }
}

// ---------------- K1: FFMA2 GEMM + alpha/exp epilogue (R2-proven) ----------------
#define XCH_STRIDE 132
#define GEMM_SMEM  (16384 * 4 + 2 * 32 * XCH_STRIDE * 4)

__global__ __launch_bounds__(256, 2)
void gemm_kernel(const float* __restrict__ X,
                 const float* __restrict__ blin,
                 const float* __restrict__ Watt,
                 float* __restrict__ out, int N) {
    extern __shared__ float sm[];
    unsigned long long* Wp = (unsigned long long*)sm;   // [k][pos] pos(q)=(q&3)*16+(q>>2)
    float* Xs = sm + 16384;                             // [buf][k][m], stride 132
    __shared__ float sWa[NHEAD * 2 * DIM];
    __shared__ float sb[DIM];

    int tid = threadIdx.x;
    for (int i = tid; i < NHEAD * 2 * DIM; i += 256) sWa[i] = Watt[i];
    if (tid < DIM) sb[tid] = blin[tid];

    for (int i = tid; i < DIM * 32; i += 256) {
        int k = i >> 5, cq = i & 31;
        float4 w4 = ((const float4*)g_WT)[i];
        int q0 = 2 * cq, q1 = 2 * cq + 1;
        int pos0 = (q0 & 3) * 16 + (q0 >> 2);
        int pos1 = (q1 & 3) * 16 + (q1 >> 2);
        unsigned long long lo, hi;
        asm("mov.b64 %0, {%1, %2};" : "=l"(lo) : "r"(__float_as_uint(w4.x)), "r"(__float_as_uint(w4.y)));
        asm("mov.b64 %0, {%1, %2};" : "=l"(hi) : "r"(__float_as_uint(w4.z)), "r"(__float_as_uint(w4.w)));
        Wp[k * 64 + pos0] = lo;
        Wp[k * 64 + pos1] = hi;
    }

    int row0 = blockIdx.x * 128;
    float4 xreg[4];

    auto loadX = [&](int ch) {
        #pragma unroll
        for (int t = 0; t < 4; t++) {
            int idx = tid + t * 256;
            int m = idx >> 3, kq = idx & 7;
            xreg[t] = make_float4(0.f, 0.f, 0.f, 0.f);
            if (row0 + m < N)
                xreg[t] = ((const float4*)X)[(size_t)(row0 + m) * 32 + ch * 8 + kq];
        }
    };
    auto storeX = [&](int buf) {
        float* base = &Xs[buf * 32 * XCH_STRIDE];
        #pragma unroll
        for (int t = 0; t < 4; t++) {
            int idx = tid + t * 256;
            int m = idx >> 3, kq = idx & 7;
            base[(kq * 4 + 0) * XCH_STRIDE + m] = xreg[t].x;
            base[(kq * 4 + 1) * XCH_STRIDE + m] = xreg[t].y;
            base[(kq * 4 + 2) * XCH_STRIDE + m] = xreg[t].z;
            base[(kq * 4 + 3) * XCH_STRIDE + m] = xreg[t].w;
        }
    };

    loadX(0); storeX(0);
    __syncthreads();

    int tx = tid & 15, ty = tid >> 4;
    int c = tx * 8;

    unsigned long long acc[8][4];
    #pragma unroll
    for (int r = 0; r < 8; r++)
        #pragma unroll
        for (int p = 0; p < 4; p++) acc[r][p] = 0ull;

    for (int ch = 0; ch < 4; ch++) {
        if (ch < 3) loadX(ch + 1);
        int buf = ch & 1;
        const float* xb = &Xs[buf * 32 * XCH_STRIDE];
        #pragma unroll 8
        for (int k = 0; k < 32; k++) {
            float4 a0 = *(const float4*)&xb[k * XCH_STRIDE + ty * 8];
            float4 a1 = *(const float4*)&xb[k * XCH_STRIDE + ty * 8 + 4];
            unsigned long long arep[8];
            const float* av = &a0.x;
            #pragma unroll
            for (int r = 0; r < 4; r++)
                asm("mov.b64 %0, {%1, %1};" : "=l"(arep[r]) : "r"(__float_as_uint(av[r])));
            const float* av1 = &a1.x;
            #pragma unroll
            for (int r = 0; r < 4; r++)
                asm("mov.b64 %0, {%1, %1};" : "=l"(arep[4 + r]) : "r"(__float_as_uint(av1[r])));
            const unsigned long long* wrow = &Wp[(ch * 32 + k) * 64];
            #pragma unroll
            for (int p = 0; p < 4; p++) {
                unsigned long long b = wrow[p * 16 + tx];
                #pragma unroll
                for (int r = 0; r < 8; r++)
                    asm("fma.rn.f32x2 %0, %1, %2, %0;" : "+l"(acc[r][p]) : "l"(arep[r]), "l"(b));
            }
        }
        if (ch < 3) {
            __syncthreads();
            storeX(buf ^ 1);
            __syncthreads();
        }
    }

    float hv[8][8];
    #pragma unroll
    for (int r = 0; r < 8; r++)
        #pragma unroll
        for (int p = 0; p < 4; p++) {
            float lo = __uint_as_float((unsigned)(acc[r][p] & 0xffffffffull));
            float hi = __uint_as_float((unsigned)(acc[r][p] >> 32));
            hv[r][2 * p]     = lo + sb[c + 2 * p];
            hv[r][2 * p + 1] = hi + sb[c + 2 * p + 1];
        }

    #pragma unroll
    for (int r = 0; r < 8; r++) {
        int row = row0 + ty * 8 + r;
        if (row < N) {
            float4 v0 = make_float4(hv[r][0], hv[r][1], hv[r][2], hv[r][3]);
            float4 v1 = make_float4(hv[r][4], hv[r][5], hv[r][6], hv[r][7]);
            ((float4*)out)[(size_t)row * 32 + tx * 2]     = v0;
            ((float4*)out)[(size_t)row * 32 + tx * 2 + 1] = v1;
            if (tx < 4) {
                ((float4*)g_h32)[row * 8 + tx * 2]     = v0;
                ((float4*)g_h32)[row * 8 + tx * 2 + 1] = v1;
            }
        }
    }

    #pragma unroll
    for (int r = 0; r < 8; r++) {
        int row = row0 + ty * 8 + r;
        float ps[NHEAD], pd[NHEAD];
        #pragma unroll
        for (int hh = 0; hh < NHEAD; hh++) {
            float s1 = 0.f, s2 = 0.f;
            #pragma unroll
            for (int j = 0; j < 8; j++) {
                s1 += hv[r][j] * sWa[hh * 2 * DIM + c + j];
                s2 += hv[r][j] * sWa[hh * 2 * DIM + DIM + c + j];
            }
            #pragma unroll
            for (int off = 8; off; off >>= 1) {
                s1 += __shfl_down_sync(0xffffffffu, s1, off, 16);
                s2 += __shfl_down_sync(0xffffffffu, s2, off, 16);
            }
            ps[hh] = s1; pd[hh] = s2;
        }
        if (tx == 0 && row < N) {
            ((float4*)g_eas)[row] = make_float4(__expf(ps[0]), __expf(ps[1]), __expf(ps[2]), __expf(ps[3]));
            ((float4*)g_ead)[row] = make_float4(__expf(pd[0]), __expf(pd[1]), __expf(pd[2]), __expf(pd[3]));
        }
    }
}

// ---------------- K2: decode (parallel branch; no alpha dependence) ----------------
__global__ __launch_bounds__(256)
void decode_kernel(const void* __restrict__ ei, int E) {
    int e = blockIdx.x * 256 + threadIdx.x;
    if (e >= E) return;
    int s, d;
    if (g_is64) {
        const long long* p = (const long long*)ei;
        s = (int)p[e]; d = (int)p[E + e];
    } else {
        const int* p = (const int*)ei;
        s = p[e]; d = p[E + e];
    }
    g_sd[e] = make_int2(s, d);
    g_rk[e] = atomicAdd(&g_cnt[d], 1);
}

// ---------------- K3a/K3b: scans (proven) ----------------
__global__ __launch_bounds__(256)
void scanA_kernel() {
    int t = threadIdx.x;
    int i = blockIdx.x * 256 + t;
    int v = (i < NMAX) ? g_cnt[i] : 0;
    int x = v;
    #pragma unroll
    for (int off = 1; off < 32; off <<= 1) {
        int y = __shfl_up_sync(0xffffffffu, x, off);
        if ((t & 31) >= off) x += y;
    }
    __shared__ int wsum[8];
    if ((t & 31) == 31) wsum[t >> 5] = x;
    __syncthreads();
    if (t < 8) {
        int y = wsum[t], z = y;
        #pragma unroll
        for (int off = 1; off < 8; off <<= 1) {
            int q = __shfl_up_sync(0xffu, z, off);
            if (t >= off) z += q;
        }
        wsum[t] = z - y;
    }
    __syncthreads();
    int excl = x - v + wsum[t >> 5];
    if (i < NMAX) g_intra[i] = excl;
    if (t == 255) g_bsum[blockIdx.x] = excl + v;
}

__global__ __launch_bounds__(512)
void scanB_kernel() {
    __shared__ int s0[512], s1[512];
    int t = threadIdx.x;
    int v = (t < NBLK) ? g_bsum[t] : 0;
    s0[t] = v;
    __syncthreads();
    int* a = s0; int* b = s1;
    for (int off = 1; off < 512; off <<= 1) {
        int x = a[t];
        if (t >= off) x += a[t - off];
        b[t] = x;
        __syncthreads();
        int* tmp = a; a = b; b = tmp;
    }
    if (t < NBLK) g_boff[t] = a[t] - v;
}

// ---------------- K4: fused CSR fill + softmax sums (after join) ----------------
__global__ __launch_bounds__(256)
void fillsums_kernel(int E) {
    int e = blockIdx.x * 256 + threadIdx.x;
    float v0 = 0.f, v1 = 0.f, v2 = 0.f, v3 = 0.f;
    if (e < E) {
        int2 sd = g_sd[e];
        g_esrc[g_boff[sd.y >> 8] + g_intra[sd.y] + g_rk[e]] = sd.x;
        float4 as = ((const float4*)g_eas)[sd.x];
        float4 ad = ((const float4*)g_ead)[sd.y];
        v0 = as.x * ad.x; v1 = as.y * ad.y; v2 = as.z * ad.z; v3 = as.w * ad.w;
    }
    #pragma unroll
    for (int off = 16; off; off >>= 1) {
        v0 += __shfl_xor_sync(0xffffffffu, v0, off);
        v1 += __shfl_xor_sync(0xffffffffu, v1, off);
        v2 += __shfl_xor_sync(0xffffffffu, v2, off);
        v3 += __shfl_xor_sync(0xffffffffu, v3, off);
    }
    __shared__ float ss[NHEAD];
    if (threadIdx.x < NHEAD) ss[threadIdx.x] = 0.f;
    __syncthreads();
    if ((threadIdx.x & 31) == 0) {
        atomicAdd(&ss[0], v0); atomicAdd(&ss[1], v1);
        atomicAdd(&ss[2], v2); atomicAdd(&ss[3], v3);
    }
    __syncthreads();
    if (threadIdx.x < NHEAD) atomicAdd(&g_sums[threadIdx.x], ss[threadIdx.x]);
}

// ---------------- K5: gather ----------------
__global__ __launch_bounds__(256)
void gather_kernel(float* __restrict__ out, int N) {
    int d = (blockIdx.x * 256 + threadIdx.x) >> 5;
    int lane = threadIdx.x & 31;
    if (d >= N) return;
    int n = g_cnt[d];
    if (n == 0) return;                 // out already holds h
    int base = g_boff[d >> 8] + g_intra[d];
    float4 fe = ((const float4*)g_ead)[d];
    float4 sm4 = *(const float4*)g_sums;
    float w0 = __fdividef(fe.x, sm4.x);
    float w1 = __fdividef(fe.y, sm4.y);
    float w2 = __fdividef(fe.z, sm4.z);
    float w3 = __fdividef(fe.w, sm4.w);
    float a0 = 0.f, a1 = 0.f, a2 = 0.f, a3 = 0.f;
    for (int i = 0; i < n; i++) {
        int s = g_esrc[base + i];
        float v = g_h32[s * HD + lane];
        float4 ea = ((const float4*)g_eas)[s];
        a0 += v * ea.x; a1 += v * ea.y; a2 += v * ea.z; a3 += v * ea.w;
    }
    float* o = out + (size_t)d * DIM + lane;
    o[0]  += a0 * w0;
    o[32] += a1 * w1;
    o[64] += a2 * w2;
    o[96] += a3 * w3;
}

// ---------------- launch (stream-forked: edge chain || GEMM) ----------------
extern "C" void kernel_launch(void* const* d_in, const int* in_sizes, int n_in,
                              void* d_out, int out_size) {
    const float* X    = (const float*)d_in[0];
    const void*  ei   = d_in[1];
    const float* Wlin = (const float*)d_in[2];
    const float* blin = (const float*)d_in[3];
    const float* Watt = (const float*)d_in[4];
    float* out = (float*)d_out;

    int N = in_sizes[0] / DIM;
    int E = in_sizes[1] / 2;

    static cudaStream_t s1 = nullptr;
    static cudaEvent_t evFork = nullptr, evJoin = nullptr;
    if (s1 == nullptr) {
        cudaStreamCreateWithFlags(&s1, cudaStreamNonBlocking);
        cudaEventCreateWithFlags(&evFork, cudaEventDisableTiming);
        cudaEventCreateWithFlags(&evJoin, cudaEventDisableTiming);
    }

    cudaFuncSetAttribute(gemm_kernel,
                         cudaFuncAttributeMaxDynamicSharedMemorySize, GEMM_SMEM);

    prep_kernel<<<200, 512>>>(Wlin, (const unsigned int*)ei);

    // fork: edge-structure chain on s1 (depends only on prep + ei)
    cudaEventRecord(evFork, 0);
    cudaStreamWaitEvent(s1, evFork, 0);
    decode_kernel<<<(E + 255) / 256, 256, 0, s1>>>(ei, E);
    scanA_kernel<<<NBLK, 256, 0, s1>>>();
    scanB_kernel<<<1, 512, 0, s1>>>();
    cudaEventRecord(evJoin, s1);

    // main stream: GEMM runs concurrently with the chain
    gemm_kernel<<<(N + 127) / 128, 256, GEMM_SMEM>>>(X, blin, Watt, out, N);

    // join, then alpha-dependent edge work
    cudaStreamWaitEvent(0, evJoin, 0);
    fillsums_kernel<<<(E + 255) / 256, 256>>>(E);
    gather_kernel<<<(N * 32 + 255) / 256, 256>>>(out, N);
}